// round 15
// baseline (speedup 1.0000x reference)
#include <cuda_runtime.h>

// Blur_by_Kernel: per-batch 21x21 cross-correlation, reflect pad 10.
// input (16,3,768,768) fp32, kernel (16,21,21) fp32.
// out[b,c,y,x] = sum_{ky,kx} in[b,c, refl(y+ky-10), refl(x+kx-10)] * w[b,ky,kx]
//
// R15 = R13 structure (407.7us best) with thread tile re-shaped CPT=16/RPT=2
// (TXN=8, TYN=16; same 128x32 CTA tile, same prologue, same 6 CTAs/SM).
// Weight-row passes amortize over 16 cols: passes/thread 84->42, weight LDS
// 504->252 (-1.5% issue slots), 22 windows instead of 24. FFMA count, tile
// geometry, prologue, epilogue unchanged -> no I$ growth.
// Revert criterion: regs > 85 or local-memory traffic.
// Measured dead ends: FFMA2 (half-rate), tensor cores (mat-vec), swizzle
// (ALU cost), 2x unroll (I$), large CTAs (barrier), do_pass2 (neutral).

namespace {
constexpr int HW   = 768;
constexpr int KS   = 21;
constexpr int PAD  = 10;
constexpr int CPT  = 16;                 // cols per thread
constexpr int RPT  = 2;                  // rows per thread
constexpr int TXN  = 8, TYN = 16;
constexpr int TILE_X = CPT * TXN;        // 128
constexpr int TILE_Y = RPT * TYN;        // 32
constexpr int SM_W = TILE_X + 2 * PAD;   // 148 floats (592B rows)
constexpr int SM_H = TILE_Y + 2 * PAD;   // 52 rows
constexpr int WSTRIDE = 24;              // padded weight row (96B)
constexpr int NT   = TXN * TYN;          // 128
}

__device__ __forceinline__ int refl_y(int gy) {
    return (gy < 0) ? -gy : ((gy >= HW) ? (2 * HW - 2 - gy) : gy);
}

// one weight-row pass over a 36-float window: acc[j] += sum_kx v[kx+j]*w[kx]
__device__ __forceinline__ void do_pass(float (&acc)[CPT],
                                        const float* __restrict__ wr,
                                        const float (&v)[36])
{
    #pragma unroll
    for (int g = 0; g < 5; ++g) {
        const float4 w = *(const float4*)(wr + 4 * g);   // broadcast LDS.128
        #pragma unroll
        for (int j = 0; j < CPT; ++j) acc[j] = fmaf(v[4*g + 0 + j], w.x, acc[j]);
        #pragma unroll
        for (int j = 0; j < CPT; ++j) acc[j] = fmaf(v[4*g + 1 + j], w.y, acc[j]);
        #pragma unroll
        for (int j = 0; j < CPT; ++j) acc[j] = fmaf(v[4*g + 2 + j], w.z, acc[j]);
        #pragma unroll
        for (int j = 0; j < CPT; ++j) acc[j] = fmaf(v[4*g + 3 + j], w.w, acc[j]);
    }
    const float wl = wr[20];
    #pragma unroll
    for (int j = 0; j < CPT; ++j) acc[j] = fmaf(v[20 + j], wl, acc[j]);
}

__global__ __launch_bounds__(NT, 6)
void blur21_kernel(const float* __restrict__ in,
                   const float* __restrict__ wts,
                   float* __restrict__ out)
{
    __shared__ float tile[SM_H][SM_W];
    __shared__ float sw[KS * WSTRIDE];

    const int bc  = blockIdx.z;           // b*3 + c
    const int b   = bc / 3;
    const int bx  = blockIdx.x * TILE_X;
    const int by  = blockIdx.y * TILE_Y;
    const int tid = threadIdx.x;

    const float* __restrict__ img = in + (size_t)bc * (HW * HW);

    // weights for this batch, rows padded to WSTRIDE (504 floats)
    for (int i = tid; i < KS * WSTRIDE; i += NT) {
        const int r = i / WSTRIDE, c = i - r * WSTRIDE;
        sw[i] = (c < KS) ? wts[b * (KS * KS) + r * KS + c] : 0.f;
    }

    // ---- vectorized prologue (identical to R13), all blocks ----
    // warp w handles rows w, w+4, ..., w+48 (13 rows, fully unrolled -> MLP).
    {
        const int w  = tid >> 5;
        const int ln = tid & 31;
        const bool left  = (bx == 0);
        const bool right = (bx + TILE_X == HW);
        const float* __restrict__ rowbase = img + (left ? 0 : (bx - 12));
        const int cbase = left ? 10 : -2;
        const int umax  = (left || right) ? 35 : 38;

        #pragma unroll
        for (int k = 0; k < 13; ++k) {
            const int r  = w + 4 * k;
            const int gy = refl_y(by + r - PAD);
            const float4* __restrict__ gp =
                (const float4*)(rowbase + (size_t)gy * HW);

            {   // unit u = ln (0..31)
                const float4 q = gp[ln];
                const int c0 = 4 * ln + cbase;
                if (c0 >= 0)          tile[r][c0]     = q.x;
                if (c0 + 1 >= 0)      tile[r][c0 + 1] = q.y;
                if (c0 + 2 < SM_W)    tile[r][c0 + 2] = q.z;
                if (c0 + 3 < SM_W)    tile[r][c0 + 3] = q.w;
            }
            if (ln < umax - 32) {     // unit u = 32+ln
                const float4 q = gp[32 + ln];
                const int c0 = 4 * (32 + ln) + cbase;
                if (c0 < SM_W)        tile[r][c0]     = q.x;
                if (c0 + 1 < SM_W)    tile[r][c0 + 1] = q.y;
                if (c0 + 2 < SM_W)    tile[r][c0 + 2] = q.z;
                if (c0 + 3 < SM_W)    tile[r][c0 + 3] = q.w;
            }
        }

        // scalar patch of the 10 x-reflected columns (edge blocks only)
        if (left || right) {
            for (int i = tid; i < 10 * SM_H; i += NT) {
                const int r = i / 10;
                const int c = i - r * 10;
                const int gy = refl_y(by + r - PAD);
                if (left)
                    tile[r][c] = img[(size_t)gy * HW + (10 - c)];
                else
                    tile[r][138 + c] = img[(size_t)gy * HW + (766 - c)];
            }
        }
    }
    __syncthreads();

    const int tx = tid & 7;               // 0..7
    const int ty = tid >> 3;              // 0..15
    const int ox = tx * CPT;              // 64B-aligned smem col base
    const int oy = ty * RPT;

    float acc0[CPT], acc1[CPT];
    #pragma unroll
    for (int j = 0; j < CPT; ++j) { acc0[j] = 0.f; acc1[j] = 0.f; }

    float v[36];
    #define LOADW(s)                                                     \
        do {                                                             \
            const float4* __restrict__ p =                               \
                (const float4*)&tile[oy + (s)][ox];                      \
            _Pragma("unroll")                                            \
            for (int i = 0; i < 9; ++i) {                                \
                const float4 q = p[i];                                   \
                v[4*i+0] = q.x; v[4*i+1] = q.y;                          \
                v[4*i+2] = q.z; v[4*i+3] = q.w;                          \
            }                                                            \
        } while (0)

    // window row s feeds output row r (0..1) with weight row (s - r)
    LOADW(0);
    do_pass(acc0, &sw[0 * WSTRIDE], v);

    #pragma unroll 1
    for (int s = 1; s <= 20; ++s) {
        LOADW(s);
        const float* __restrict__ w0 = &sw[s * WSTRIDE];
        do_pass(acc0, w0, v);
        do_pass(acc1, w0 - WSTRIDE, v);
    }

    LOADW(21);
    do_pass(acc1, &sw[20 * WSTRIDE], v);

    #undef LOADW

    // streaming stores: output is write-once, never re-read
    float* __restrict__ o = out + (size_t)bc * (HW * HW)
                                + (size_t)(by + oy) * HW + (bx + ox);
    __stcs((float4*)(o),           make_float4(acc0[0],  acc0[1],  acc0[2],  acc0[3]));
    __stcs((float4*)(o + 4),       make_float4(acc0[4],  acc0[5],  acc0[6],  acc0[7]));
    __stcs((float4*)(o + 8),       make_float4(acc0[8],  acc0[9],  acc0[10], acc0[11]));
    __stcs((float4*)(o + 12),      make_float4(acc0[12], acc0[13], acc0[14], acc0[15]));
    __stcs((float4*)(o + HW),      make_float4(acc1[0],  acc1[1],  acc1[2],  acc1[3]));
    __stcs((float4*)(o + HW + 4),  make_float4(acc1[4],  acc1[5],  acc1[6],  acc1[7]));
    __stcs((float4*)(o + HW + 8),  make_float4(acc1[8],  acc1[9],  acc1[10], acc1[11]));
    __stcs((float4*)(o + HW + 12), make_float4(acc1[12], acc1[13], acc1[14], acc1[15]));
}

extern "C" void kernel_launch(void* const* d_in, const int* in_sizes, int n_in,
                              void* d_out, int out_size)
{
    const float* img = (const float*)d_in[0];
    const float* wts = (const float*)d_in[1];
    if (n_in >= 2 && in_sizes[0] == 16 * KS * KS) {   // 7056 -> kernel tensor
        img = (const float*)d_in[1];
        wts = (const float*)d_in[0];
    }

    dim3 grid(HW / TILE_X, HW / TILE_Y, 16 * 3);
    blur21_kernel<<<grid, NT>>>(img, wts, (float*)d_out);
}

// round 16
// speedup vs baseline: 1.0841x; 1.0841x over previous
#include <cuda_runtime.h>

// Blur_by_Kernel: per-batch 21x21 cross-correlation, reflect pad 10.
// input (16,3,768,768) fp32, kernel (16,21,21) fp32.
// out[b,c,y,x] = sum_{ky,kx} in[b,c, refl(y+ky-10), refl(x+kx-10)] * w[b,ky,kx]
//
// FINAL = R13/R11, the measured optimum (407.7us):
//  - 128-thread CTAs, 128x32 output tile, 6 CTAs/SM (24 warps; regfile+smem cap)
//  - scalar-FFMA sliding-window mainloop: one 28-float register window per smem
//    row, reused by RPT=4 output rows; CPT=8 (32B lane stride = 2-way-conflict
//    sweet spot; R15 proved CPT=16's 64B stride goes 4-way and loses 9%)
//  - ROLLED interior (R12: 2x unroll blows L0/L1.5 I$ -> L2 instr streaming)
//  - uniform vectorized prologue: batched LDG.128 rows (high MLP; R7 proved
//    serializing these to MLP=1 costs ~60us) + edge column patch
//  - __stcs streaming epilogue (output write-once)
// Measured dead ends: FFMA2 (half-rate on sm_103a), tensor cores (per-(b,c)
// matrix-vector, N=1), smem swizzle (ALU cost > conflict win), large CTAs
// (barrier skew kills independent-CTA overlap), pass-merging (neutral; ptxas
// already cross-schedules), 7 CTAs/SM (smem+regfile), persistent CTAs (same
// ceil(6912/888) tail).

namespace {
constexpr int HW   = 768;
constexpr int KS   = 21;
constexpr int PAD  = 10;
constexpr int CPT  = 8;                  // cols per thread
constexpr int RPT  = 4;                  // rows per thread
constexpr int TXN  = 16, TYN = 8;
constexpr int TILE_X = CPT * TXN;        // 128
constexpr int TILE_Y = RPT * TYN;        // 32
constexpr int SM_W = TILE_X + 2 * PAD;   // 148 floats (592B rows)
constexpr int SM_H = TILE_Y + 2 * PAD;   // 52 rows
constexpr int WSTRIDE = 24;              // padded weight row (96B)
constexpr int NT   = TXN * TYN;          // 128
}

__device__ __forceinline__ int refl_y(int gy) {
    return (gy < 0) ? -gy : ((gy >= HW) ? (2 * HW - 2 - gy) : gy);
}

// one weight-row pass: acc[j] += sum_kx v[kx+j] * w[kx]
__device__ __forceinline__ void do_pass(float (&acc)[CPT],
                                        const float* __restrict__ wr,
                                        const float (&v)[28])
{
    #pragma unroll
    for (int g = 0; g < 5; ++g) {
        const float4 w = *(const float4*)(wr + 4 * g);   // broadcast LDS.128
        #pragma unroll
        for (int j = 0; j < CPT; ++j) acc[j] = fmaf(v[4*g + 0 + j], w.x, acc[j]);
        #pragma unroll
        for (int j = 0; j < CPT; ++j) acc[j] = fmaf(v[4*g + 1 + j], w.y, acc[j]);
        #pragma unroll
        for (int j = 0; j < CPT; ++j) acc[j] = fmaf(v[4*g + 2 + j], w.z, acc[j]);
        #pragma unroll
        for (int j = 0; j < CPT; ++j) acc[j] = fmaf(v[4*g + 3 + j], w.w, acc[j]);
    }
    const float wl = wr[20];
    #pragma unroll
    for (int j = 0; j < CPT; ++j) acc[j] = fmaf(v[20 + j], wl, acc[j]);
}

__global__ __launch_bounds__(NT, 6)
void blur21_kernel(const float* __restrict__ in,
                   const float* __restrict__ wts,
                   float* __restrict__ out)
{
    __shared__ float tile[SM_H][SM_W];
    __shared__ float sw[KS * WSTRIDE];

    const int bc  = blockIdx.z;           // b*3 + c
    const int b   = bc / 3;
    const int bx  = blockIdx.x * TILE_X;
    const int by  = blockIdx.y * TILE_Y;
    const int tid = threadIdx.x;

    const float* __restrict__ img = in + (size_t)bc * (HW * HW);

    // weights for this batch, rows padded to WSTRIDE (504 floats)
    for (int i = tid; i < KS * WSTRIDE; i += NT) {
        const int r = i / WSTRIDE, c = i - r * WSTRIDE;
        sw[i] = (c < KS) ? wts[b * (KS * KS) + r * KS + c] : 0.f;
    }

    // ---- vectorized prologue, all blocks ----
    // warp w handles rows w, w+4, ..., w+48 (13 rows, fully unrolled -> MLP).
    {
        const int w  = tid >> 5;
        const int ln = tid & 31;
        const bool left  = (bx == 0);
        const bool right = (bx + TILE_X == HW);
        // aligned gmem float4 base and col mapping:
        //   interior/right: base gx = bx-12, unit u -> c0 = 4u-2, u < 35|38
        //   left:           base gx = 0,     unit u -> c0 = 4u+10, u < 35
        const float* __restrict__ rowbase = img + (left ? 0 : (bx - 12));
        const int cbase = left ? 10 : -2;
        const int umax  = (left || right) ? 35 : 38;

        #pragma unroll
        for (int k = 0; k < 13; ++k) {
            const int r  = w + 4 * k;
            const int gy = refl_y(by + r - PAD);
            const float4* __restrict__ gp =
                (const float4*)(rowbase + (size_t)gy * HW);

            {   // unit u = ln (0..31)
                const float4 q = gp[ln];
                const int c0 = 4 * ln + cbase;
                if (c0 >= 0)          tile[r][c0]     = q.x;
                if (c0 + 1 >= 0)      tile[r][c0 + 1] = q.y;
                if (c0 + 2 < SM_W)    tile[r][c0 + 2] = q.z;
                if (c0 + 3 < SM_W)    tile[r][c0 + 3] = q.w;
            }
            if (ln < umax - 32) {     // unit u = 32+ln
                const float4 q = gp[32 + ln];
                const int c0 = 4 * (32 + ln) + cbase;
                if (c0 < SM_W)        tile[r][c0]     = q.x;
                if (c0 + 1 < SM_W)    tile[r][c0 + 1] = q.y;
                if (c0 + 2 < SM_W)    tile[r][c0 + 2] = q.z;
                if (c0 + 3 < SM_W)    tile[r][c0 + 3] = q.w;
            }
        }

        // scalar patch of the 10 x-reflected columns (edge blocks only):
        //   left : cols 0..9     <- gx = 10 - c          (reflect of -10..-1)
        //   right: cols 138..147 <- gx = 766 - (c - 138) (reflect of 768..777)
        if (left || right) {
            for (int i = tid; i < 10 * SM_H; i += NT) {
                const int r = i / 10;
                const int c = i - r * 10;
                const int gy = refl_y(by + r - PAD);
                if (left)
                    tile[r][c] = img[(size_t)gy * HW + (10 - c)];
                else
                    tile[r][138 + c] = img[(size_t)gy * HW + (766 - c)];
            }
        }
    }
    __syncthreads();

    const int tx = tid & 15;              // 0..15
    const int ty = tid >> 4;              // 0..7
    const int ox = tx * CPT;              // 32B-aligned smem col base
    const int oy = ty * RPT;

    float acc0[CPT], acc1[CPT], acc2[CPT], acc3[CPT];
    #pragma unroll
    for (int j = 0; j < CPT; ++j) {
        acc0[j] = 0.f; acc1[j] = 0.f; acc2[j] = 0.f; acc3[j] = 0.f;
    }

    float v[28];
    #define LOADW(s)                                                     \
        do {                                                             \
            const float4* __restrict__ p =                               \
                (const float4*)&tile[oy + (s)][ox];                      \
            _Pragma("unroll")                                            \
            for (int i = 0; i < 7; ++i) {                                \
                const float4 q = p[i];                                   \
                v[4*i+0] = q.x; v[4*i+1] = q.y;                          \
                v[4*i+2] = q.z; v[4*i+3] = q.w;                          \
            }                                                            \
        } while (0)

    // window row s feeds output row r (0..3) with weight row (s - r)
    LOADW(0);
    do_pass(acc0, &sw[0 * WSTRIDE], v);

    LOADW(1);
    do_pass(acc0, &sw[1 * WSTRIDE], v);
    do_pass(acc1, &sw[0 * WSTRIDE], v);

    LOADW(2);
    do_pass(acc0, &sw[2 * WSTRIDE], v);
    do_pass(acc1, &sw[1 * WSTRIDE], v);
    do_pass(acc2, &sw[0 * WSTRIDE], v);

    #pragma unroll 1
    for (int s = 3; s <= 20; ++s) {
        LOADW(s);
        const float* __restrict__ w0 = &sw[s * WSTRIDE];
        do_pass(acc0, w0, v);
        do_pass(acc1, w0 - WSTRIDE, v);
        do_pass(acc2, w0 - 2 * WSTRIDE, v);
        do_pass(acc3, w0 - 3 * WSTRIDE, v);
    }

    LOADW(21);
    do_pass(acc1, &sw[20 * WSTRIDE], v);
    do_pass(acc2, &sw[19 * WSTRIDE], v);
    do_pass(acc3, &sw[18 * WSTRIDE], v);

    LOADW(22);
    do_pass(acc2, &sw[20 * WSTRIDE], v);
    do_pass(acc3, &sw[19 * WSTRIDE], v);

    LOADW(23);
    do_pass(acc3, &sw[20 * WSTRIDE], v);

    #undef LOADW

    // streaming stores: output is write-once, never re-read
    float* __restrict__ o = out + (size_t)bc * (HW * HW)
                                + (size_t)(by + oy) * HW + (bx + ox);
    __stcs((float4*)(o),              make_float4(acc0[0], acc0[1], acc0[2], acc0[3]));
    __stcs((float4*)(o + 4),          make_float4(acc0[4], acc0[5], acc0[6], acc0[7]));
    __stcs((float4*)(o + HW),         make_float4(acc1[0], acc1[1], acc1[2], acc1[3]));
    __stcs((float4*)(o + HW + 4),     make_float4(acc1[4], acc1[5], acc1[6], acc1[7]));
    __stcs((float4*)(o + 2 * HW),     make_float4(acc2[0], acc2[1], acc2[2], acc2[3]));
    __stcs((float4*)(o + 2 * HW + 4), make_float4(acc2[4], acc2[5], acc2[6], acc2[7]));
    __stcs((float4*)(o + 3 * HW),     make_float4(acc3[0], acc3[1], acc3[2], acc3[3]));
    __stcs((float4*)(o + 3 * HW + 4), make_float4(acc3[4], acc3[5], acc3[6], acc3[7]));
}

extern "C" void kernel_launch(void* const* d_in, const int* in_sizes, int n_in,
                              void* d_out, int out_size)
{
    const float* img = (const float*)d_in[0];
    const float* wts = (const float*)d_in[1];
    if (n_in >= 2 && in_sizes[0] == 16 * KS * KS) {   // 7056 -> kernel tensor
        img = (const float*)d_in[1];
        wts = (const float*)d_in[0];
    }

    dim3 grid(HW / TILE_X, HW / TILE_Y, 16 * 3);
    blur21_kernel<<<grid, NT>>>(img, wts, (float*)d_out);
}

// round 17
// speedup vs baseline: 1.0864x; 1.0021x over previous
#include <cuda_runtime.h>

// Blur_by_Kernel: per-batch 21x21 cross-correlation, reflect pad 10.
// input (16,3,768,768) fp32, kernel (16,21,21) fp32.
// out[b,c,y,x] = sum_{ky,kx} in[b,c, refl(y+ky-10), refl(x+kx-10)] * w[b,ky,kx]
//
// CONVERGED OPTIMUM (R13/R16, 407.7us; reproduced twice):
//  - 128-thread CTAs, 128x32 output tile, 6 CTAs/SM (24 warps; regfile+smem cap)
//  - scalar-FFMA sliding-window mainloop: one 28-float register window per smem
//    row, reused by RPT=4 output rows; CPT=8 = 32B lane stride (R15: 64B stride
//    goes 4-way bank-conflicted, -9%)
//  - ROLLED interior (R12: 2x unroll -> I$ blows L0/L1.5 -> L2 instr streaming)
//  - uniform vectorized prologue: batched LDG.128 rows, high MLP (R7: MLP=1
//    serialization costs ~60us) + scalar patch of reflected edge columns
//  - __stcs streaming epilogue (output write-once)
// Measured dead ends: FFMA2 (half-rate), tensor cores (per-(b,c) mat-vec N=1),
// smem swizzle (ALU > conflict win), large CTAs (barrier skew), pass-merging
// (neutral), CPT=16 (4-way conflicts), RPT=6 (11% wave tail + 20 warps),
// 7 CTAs/SM (caps), persistent CTAs (same tail), unroll (I$).
// Issued-slot mix at optimum: 90% FFMA, 86% issue efficiency.

namespace {
constexpr int HW   = 768;
constexpr int KS   = 21;
constexpr int PAD  = 10;
constexpr int CPT  = 8;                  // cols per thread
constexpr int RPT  = 4;                  // rows per thread
constexpr int TXN  = 16, TYN = 8;
constexpr int TILE_X = CPT * TXN;        // 128
constexpr int TILE_Y = RPT * TYN;        // 32
constexpr int SM_W = TILE_X + 2 * PAD;   // 148 floats (592B rows)
constexpr int SM_H = TILE_Y + 2 * PAD;   // 52 rows
constexpr int WSTRIDE = 24;              // padded weight row (96B)
constexpr int NT   = TXN * TYN;          // 128
}

__device__ __forceinline__ int refl_y(int gy) {
    return (gy < 0) ? -gy : ((gy >= HW) ? (2 * HW - 2 - gy) : gy);
}

// one weight-row pass: acc[j] += sum_kx v[kx+j] * w[kx]
__device__ __forceinline__ void do_pass(float (&acc)[CPT],
                                        const float* __restrict__ wr,
                                        const float (&v)[28])
{
    #pragma unroll
    for (int g = 0; g < 5; ++g) {
        const float4 w = *(const float4*)(wr + 4 * g);   // broadcast LDS.128
        #pragma unroll
        for (int j = 0; j < CPT; ++j) acc[j] = fmaf(v[4*g + 0 + j], w.x, acc[j]);
        #pragma unroll
        for (int j = 0; j < CPT; ++j) acc[j] = fmaf(v[4*g + 1 + j], w.y, acc[j]);
        #pragma unroll
        for (int j = 0; j < CPT; ++j) acc[j] = fmaf(v[4*g + 2 + j], w.z, acc[j]);
        #pragma unroll
        for (int j = 0; j < CPT; ++j) acc[j] = fmaf(v[4*g + 3 + j], w.w, acc[j]);
    }
    const float wl = wr[20];
    #pragma unroll
    for (int j = 0; j < CPT; ++j) acc[j] = fmaf(v[20 + j], wl, acc[j]);
}

__global__ __launch_bounds__(NT, 6)
void blur21_kernel(const float* __restrict__ in,
                   const float* __restrict__ wts,
                   float* __restrict__ out)
{
    __shared__ float tile[SM_H][SM_W];
    __shared__ float sw[KS * WSTRIDE];

    const int bc  = blockIdx.z;           // b*3 + c
    const int b   = bc / 3;
    const int bx  = blockIdx.x * TILE_X;
    const int by  = blockIdx.y * TILE_Y;
    const int tid = threadIdx.x;

    const float* __restrict__ img = in + (size_t)bc * (HW * HW);

    // weights for this batch, rows padded to WSTRIDE (504 floats)
    for (int i = tid; i < KS * WSTRIDE; i += NT) {
        const int r = i / WSTRIDE, c = i - r * WSTRIDE;
        sw[i] = (c < KS) ? wts[b * (KS * KS) + r * KS + c] : 0.f;
    }

    // ---- vectorized prologue, all blocks ----
    // warp w handles rows w, w+4, ..., w+48 (13 rows, fully unrolled -> MLP).
    {
        const int w  = tid >> 5;
        const int ln = tid & 31;
        const bool left  = (bx == 0);
        const bool right = (bx + TILE_X == HW);
        // aligned gmem float4 base and col mapping:
        //   interior/right: base gx = bx-12, unit u -> c0 = 4u-2, u < 35|38
        //   left:           base gx = 0,     unit u -> c0 = 4u+10, u < 35
        const float* __restrict__ rowbase = img + (left ? 0 : (bx - 12));
        const int cbase = left ? 10 : -2;
        const int umax  = (left || right) ? 35 : 38;

        #pragma unroll
        for (int k = 0; k < 13; ++k) {
            const int r  = w + 4 * k;
            const int gy = refl_y(by + r - PAD);
            const float4* __restrict__ gp =
                (const float4*)(rowbase + (size_t)gy * HW);

            {   // unit u = ln (0..31)
                const float4 q = gp[ln];
                const int c0 = 4 * ln + cbase;
                if (c0 >= 0)          tile[r][c0]     = q.x;
                if (c0 + 1 >= 0)      tile[r][c0 + 1] = q.y;
                if (c0 + 2 < SM_W)    tile[r][c0 + 2] = q.z;
                if (c0 + 3 < SM_W)    tile[r][c0 + 3] = q.w;
            }
            if (ln < umax - 32) {     // unit u = 32+ln
                const float4 q = gp[32 + ln];
                const int c0 = 4 * (32 + ln) + cbase;
                if (c0 < SM_W)        tile[r][c0]     = q.x;
                if (c0 + 1 < SM_W)    tile[r][c0 + 1] = q.y;
                if (c0 + 2 < SM_W)    tile[r][c0 + 2] = q.z;
                if (c0 + 3 < SM_W)    tile[r][c0 + 3] = q.w;
            }
        }

        // scalar patch of the 10 x-reflected columns (edge blocks only):
        //   left : cols 0..9     <- gx = 10 - c          (reflect of -10..-1)
        //   right: cols 138..147 <- gx = 766 - (c - 138) (reflect of 768..777)
        if (left || right) {
            for (int i = tid; i < 10 * SM_H; i += NT) {
                const int r = i / 10;
                const int c = i - r * 10;
                const int gy = refl_y(by + r - PAD);
                if (left)
                    tile[r][c] = img[(size_t)gy * HW + (10 - c)];
                else
                    tile[r][138 + c] = img[(size_t)gy * HW + (766 - c)];
            }
        }
    }
    __syncthreads();

    const int tx = tid & 15;              // 0..15
    const int ty = tid >> 4;              // 0..7
    const int ox = tx * CPT;              // 32B-aligned smem col base
    const int oy = ty * RPT;

    float acc0[CPT], acc1[CPT], acc2[CPT], acc3[CPT];
    #pragma unroll
    for (int j = 0; j < CPT; ++j) {
        acc0[j] = 0.f; acc1[j] = 0.f; acc2[j] = 0.f; acc3[j] = 0.f;
    }

    float v[28];
    #define LOADW(s)                                                     \
        do {                                                             \
            const float4* __restrict__ p =                               \
                (const float4*)&tile[oy + (s)][ox];                      \
            _Pragma("unroll")                                            \
            for (int i = 0; i < 7; ++i) {                                \
                const float4 q = p[i];                                   \
                v[4*i+0] = q.x; v[4*i+1] = q.y;                          \
                v[4*i+2] = q.z; v[4*i+3] = q.w;                          \
            }                                                            \
        } while (0)

    // window row s feeds output row r (0..3) with weight row (s - r)
    LOADW(0);
    do_pass(acc0, &sw[0 * WSTRIDE], v);

    LOADW(1);
    do_pass(acc0, &sw[1 * WSTRIDE], v);
    do_pass(acc1, &sw[0 * WSTRIDE], v);

    LOADW(2);
    do_pass(acc0, &sw[2 * WSTRIDE], v);
    do_pass(acc1, &sw[1 * WSTRIDE], v);
    do_pass(acc2, &sw[0 * WSTRIDE], v);

    #pragma unroll 1
    for (int s = 3; s <= 20; ++s) {
        LOADW(s);
        const float* __restrict__ w0 = &sw[s * WSTRIDE];
        do_pass(acc0, w0, v);
        do_pass(acc1, w0 - WSTRIDE, v);
        do_pass(acc2, w0 - 2 * WSTRIDE, v);
        do_pass(acc3, w0 - 3 * WSTRIDE, v);
    }

    LOADW(21);
    do_pass(acc1, &sw[20 * WSTRIDE], v);
    do_pass(acc2, &sw[19 * WSTRIDE], v);
    do_pass(acc3, &sw[18 * WSTRIDE], v);

    LOADW(22);
    do_pass(acc2, &sw[20 * WSTRIDE], v);
    do_pass(acc3, &sw[19 * WSTRIDE], v);

    LOADW(23);
    do_pass(acc3, &sw[20 * WSTRIDE], v);

    #undef LOADW

    // streaming stores: output is write-once, never re-read
    float* __restrict__ o = out + (size_t)bc * (HW * HW)
                                + (size_t)(by + oy) * HW + (bx + ox);
    __stcs((float4*)(o),              make_float4(acc0[0], acc0[1], acc0[2], acc0[3]));
    __stcs((float4*)(o + 4),          make_float4(acc0[4], acc0[5], acc0[6], acc0[7]));
    __stcs((float4*)(o + HW),         make_float4(acc1[0], acc1[1], acc1[2], acc1[3]));
    __stcs((float4*)(o + HW + 4),     make_float4(acc1[4], acc1[5], acc1[6], acc1[7]));
    __stcs((float4*)(o + 2 * HW),     make_float4(acc2[0], acc2[1], acc2[2], acc2[3]));
    __stcs((float4*)(o + 2 * HW + 4), make_float4(acc2[4], acc2[5], acc2[6], acc2[7]));
    __stcs((float4*)(o + 3 * HW),     make_float4(acc3[0], acc3[1], acc3[2], acc3[3]));
    __stcs((float4*)(o + 3 * HW + 4), make_float4(acc3[4], acc3[5], acc3[6], acc3[7]));
}

extern "C" void kernel_launch(void* const* d_in, const int* in_sizes, int n_in,
                              void* d_out, int out_size)
{
    const float* img = (const float*)d_in[0];
    const float* wts = (const float*)d_in[1];
    if (n_in >= 2 && in_sizes[0] == 16 * KS * KS) {   // 7056 -> kernel tensor
        img = (const float*)d_in[1];
        wts = (const float*)d_in[0];
    }

    dim3 grid(HW / TILE_X, HW / TILE_Y, 16 * 3);
    blur21_kernel<<<grid, NT>>>(img, wts, (float*)d_out);
}